// round 12
// baseline (speedup 1.0000x reference)
#include <cuda_runtime.h>
#include <cuda_fp16.h>
#include <cstdint>

#define NN 100000
#define NE 1600000
#define TOT (NE + NN)
#define HD 128

union H2U { unsigned int u; __half2 h; };
__device__ __forceinline__ unsigned int h2_to_u(__half2 h) { H2U c; c.h = h; return c.u; }
__device__ __forceinline__ __half2 u_to_h2(unsigned int u) { H2U c; c.u = u; return c.h; }

union F2U { unsigned long long u; float2 f; };
__device__ __forceinline__ unsigned long long dup_f32x2(float a) {
    unsigned long long r;
    asm("mov.b64 %0, {%1, %1};" : "=l"(r) : "f"(a));
    return r;
}
__device__ __forceinline__ void ffma2(unsigned long long& d, unsigned long long a,
                                      unsigned long long b) {
    asm("fma.rn.f32x2 %0, %1, %2, %0;" : "+l"(d) : "l"(a), "l"(b));
}

// ---------------- scratch (device globals; no allocation allowed) ------------
__device__ uint4  g_h16a[NN * 16];   // fp16 h0 (alpha term, written by gemm1)
__device__ uint4  g_h16b[NN * 16];   // fp16 ping
__device__ uint4  g_h16c[NN * 16];   // fp16 pong (final h lands here, t=9)
__device__ int    g_cnt[NN];
__device__ int    g_fill[NN];
__device__ float  g_dinv[NN];
__device__ int    g_rowptr[NN + 1];
__device__ int2   g_ew[TOT];         // .x = src col, .y = float bits of 0.9*w
__device__ int    g_bsum[64];
__device__ int    g_is64;

// ---------------- init counters + edge dtype detection -----------------------
__global__ void initdet(const int* ei32) {
    int n = blockIdx.x * blockDim.x + threadIdx.x;
    if (n < NN) { g_cnt[n] = 1; g_fill[n] = 0; }
    if (blockIdx.x == 0 && threadIdx.x < 32) {
        int lane = threadIdx.x;
        int orv = 0;
        for (int i = lane; i < 1024; i += 32) orv |= ei32[2 * i + 1];
        #pragma unroll
        for (int off = 16; off; off >>= 1) orv |= __shfl_xor_sync(0xFFFFFFFFu, orv, off);
        if (lane == 0) g_is64 = (orv == 0) ? 1 : 0;
    }
}

__device__ __forceinline__ int edge_src(const void* ei, int e) {
    if (g_is64) return (int)((const long long*)ei)[e];
    return ((const int*)ei)[e];
}
__device__ __forceinline__ int edge_dst(const void* ei, int e) {
    if (g_is64) return (int)((const long long*)ei)[NE + e];
    return ((const int*)ei)[NE + e];
}

__global__ void hist(const void* __restrict__ ei) {
    int e = blockIdx.x * blockDim.x + threadIdx.x;
    if (e < NE) atomicAdd(&g_cnt[edge_dst(ei, e)], 1);
}

__global__ void scan1() {
    __shared__ int sh[256];
    int tid = threadIdx.x;
    int base = blockIdx.x * 2048 + tid * 8;
    int v[8];
    int s = 0;
    #pragma unroll
    for (int i = 0; i < 8; i++) {
        int idx = base + i;
        v[i] = (idx < NN) ? g_cnt[idx] : 0;
        if (idx < NN) g_dinv[idx] = rsqrtf((float)v[i]);
        s += v[i];
    }
    sh[tid] = s;
    __syncthreads();
    for (int off = 1; off < 256; off <<= 1) {
        int t = (tid >= off) ? sh[tid - off] : 0;
        __syncthreads();
        sh[tid] += t;
        __syncthreads();
    }
    int run = sh[tid] - s;
    #pragma unroll
    for (int i = 0; i < 8; i++) {
        int idx = base + i;
        if (idx < NN) g_rowptr[idx] = run;
        run += v[i];
    }
    if (tid == 255) g_bsum[blockIdx.x] = sh[255];
}

__global__ void scanfix() {
    __shared__ int soff;
    int idx = blockIdx.x * blockDim.x + threadIdx.x;
    int sblk = (blockIdx.x * 256) >> 11;
    if (threadIdx.x == 0) {
        int a = 0;
        for (int i = 0; i < sblk; i++) a += g_bsum[i];
        soff = a;
    }
    __syncthreads();
    if (idx < NN) g_rowptr[idx] += soff;
    if (idx == 0) g_rowptr[NN] = TOT;
}

__global__ void scatter(const void* __restrict__ ei) {
    int e = blockIdx.x * blockDim.x + threadIdx.x;
    if (e < NE) {
        int s = edge_src(ei, e);
        int d = edge_dst(ei, e);
        int pos = g_rowptr[d] + atomicAdd(&g_fill[d], 1);
        float ww = 0.9f * g_dinv[s] * g_dinv[d];
        g_ew[pos] = make_int2(s, __float_as_int(ww));
    } else if (e < TOT) {
        int n = e - NE;
        int pos = g_rowptr[n] + atomicAdd(&g_fill[n], 1);
        float di = g_dinv[n];
        g_ew[pos] = make_int2(n, __float_as_int(0.9f * di * di));
    }
}

// ---------------- 128-tile SGEMM with packed f32x2 FMA ------------------------
// Xin: fp32 (inhalf=0) or fp16-uint2 rows (inhalf=1).
// mode 1: relu + write fp16 h0 to g_h16a. mode 0: fp32 out.
__global__ __launch_bounds__(256) void gemm128(
    const void* __restrict__ Xin, const float* __restrict__ Wm,
    const float* __restrict__ bias, float* __restrict__ out,
    int mode, int inhalf)
{
    __shared__ float As[128][33];
    __shared__ float Bs[32][128];

    int tid = threadIdx.x;
    int tx = tid & 15;
    int ty = tid >> 4;
    int rowBase = blockIdx.x * 128;

    unsigned long long acc[32];   // [i][j2] packed pairs over columns
    #pragma unroll
    for (int i = 0; i < 32; i++) acc[i] = 0ull;

    for (int kc = 0; kc < 4; kc++) {
        #pragma unroll
        for (int l = 0; l < 4; l++) {
            int idx = tid + l * 256;
            int r  = idx >> 3;
            int kq = idx & 7;
            int row = rowBase + r;
            float4 v = make_float4(0.f, 0.f, 0.f, 0.f);
            if (row < NN) {
                if (inhalf) {
                    uint2 hv = reinterpret_cast<const uint2*>(Xin)[row * 32 + kc * 8 + kq];
                    float2 lo = __half22float2(u_to_h2(hv.x));
                    float2 hi = __half22float2(u_to_h2(hv.y));
                    v = make_float4(lo.x, lo.y, hi.x, hi.y);
                } else {
                    v = reinterpret_cast<const float4*>(Xin)[row * 32 + kc * 8 + kq];
                }
            }
            As[r][kq * 4 + 0] = v.x;
            As[r][kq * 4 + 1] = v.y;
            As[r][kq * 4 + 2] = v.z;
            As[r][kq * 4 + 3] = v.w;
        }
        #pragma unroll
        for (int l = 0; l < 4; l++) {
            int idx = tid + l * 256;
            int k  = idx >> 5;
            int cq = idx & 31;
            reinterpret_cast<float4*>(&Bs[k][0])[cq] =
                reinterpret_cast<const float4*>(Wm)[(kc * 32 + k) * 32 + cq];
        }
        __syncthreads();

        #pragma unroll
        for (int k = 0; k < 32; k++) {
            // b pairs: 4x 64-bit loads, bit-identical to f32x2 lanes
            const unsigned long long* bp =
                reinterpret_cast<const unsigned long long*>(&Bs[k][tx * 8]);
            unsigned long long b2[4];
            b2[0] = bp[0]; b2[1] = bp[1]; b2[2] = bp[2]; b2[3] = bp[3];
            #pragma unroll
            for (int i = 0; i < 8; i++) {
                unsigned long long a2 = dup_f32x2(As[ty * 8 + i][k]);
                ffma2(acc[i * 4 + 0], a2, b2[0]);
                ffma2(acc[i * 4 + 1], a2, b2[1]);
                ffma2(acc[i * 4 + 2], a2, b2[2]);
                ffma2(acc[i * 4 + 3], a2, b2[3]);
            }
        }
        __syncthreads();
    }

    float bb[8];
    *(float4*)&bb[0] = *(const float4*)&bias[tx * 8];
    *(float4*)&bb[4] = *(const float4*)&bias[tx * 8 + 4];

    #pragma unroll
    for (int i = 0; i < 8; i++) {
        int row = rowBase + ty * 8 + i;
        if (row < NN) {
            float o[8];
            #pragma unroll
            for (int j2 = 0; j2 < 4; j2++) {
                F2U c; c.u = acc[i * 4 + j2];
                o[j2 * 2 + 0] = c.f.x + bb[j2 * 2 + 0];
                o[j2 * 2 + 1] = c.f.y + bb[j2 * 2 + 1];
            }
            if (mode) {
                #pragma unroll
                for (int j = 0; j < 8; j++) o[j] = fmaxf(o[j], 0.f);
                uint4 u;
                u.x = h2_to_u(__floats2half2_rn(o[0], o[1]));
                u.y = h2_to_u(__floats2half2_rn(o[2], o[3]));
                u.z = h2_to_u(__floats2half2_rn(o[4], o[5]));
                u.w = h2_to_u(__floats2half2_rn(o[6], o[7]));
                g_h16a[row * 16 + tx] = u;
            } else {
                float4* op = reinterpret_cast<float4*>(out + row * HD + tx * 8);
                op[0] = *(float4*)&o[0];
                op[1] = *(float4*)&o[4];
            }
        }
    }
}

// ---------------- APPNP propagation: 16 threads/node, uint4 fp16 gathers -----
// t=0: in=g_h16a(h0). t>=1: in = (t odd ? g_h16b : g_h16c).
// out = (t odd ? g_h16c : g_h16b). alpha term always from g_h16a.
__global__ __launch_bounds__(256) void propagate(int t) {
    int idx = blockIdx.x * blockDim.x + threadIdx.x;
    int node = idx >> 4;
    int lane = idx & 15;
    if (node >= NN) return;

    const uint4* __restrict__ hin =
        (t == 0) ? g_h16a : ((t & 1) ? g_h16b : g_h16c);
    uint4* __restrict__ hout = (t & 1) ? g_h16c : g_h16b;

    int beg = g_rowptr[node];
    int end = g_rowptr[node + 1];

    float a0 = 0.f, a1 = 0.f, a2 = 0.f, a3 = 0.f;
    float a4 = 0.f, a5 = 0.f, a6 = 0.f, a7 = 0.f;
    #pragma unroll 4
    for (int e = beg; e < end; e++) {
        int2 ew = __ldg(&g_ew[e]);
        float ww = __int_as_float(ew.y);
        uint4 hv = __ldg(&hin[ew.x * 16 + lane]);
        float2 f0 = __half22float2(u_to_h2(hv.x));
        float2 f1 = __half22float2(u_to_h2(hv.y));
        float2 f2 = __half22float2(u_to_h2(hv.z));
        float2 f3 = __half22float2(u_to_h2(hv.w));
        a0 = fmaf(ww, f0.x, a0); a1 = fmaf(ww, f0.y, a1);
        a2 = fmaf(ww, f1.x, a2); a3 = fmaf(ww, f1.y, a3);
        a4 = fmaf(ww, f2.x, a4); a5 = fmaf(ww, f2.y, a5);
        a6 = fmaf(ww, f3.x, a6); a7 = fmaf(ww, f3.y, a7);
    }

    uint4 zv = __ldg(&g_h16a[node * 16 + lane]);
    float2 z0 = __half22float2(u_to_h2(zv.x));
    float2 z1 = __half22float2(u_to_h2(zv.y));
    float2 z2 = __half22float2(u_to_h2(zv.z));
    float2 z3 = __half22float2(u_to_h2(zv.w));
    float o0 = a0 + 0.1f * z0.x, o1 = a1 + 0.1f * z0.y;
    float o2 = a2 + 0.1f * z1.x, o3 = a3 + 0.1f * z1.y;
    float o4 = a4 + 0.1f * z2.x, o5 = a5 + 0.1f * z2.y;
    float o6 = a6 + 0.1f * z3.x, o7 = a7 + 0.1f * z3.y;

    uint4 u;
    u.x = h2_to_u(__floats2half2_rn(o0, o1));
    u.y = h2_to_u(__floats2half2_rn(o2, o3));
    u.z = h2_to_u(__floats2half2_rn(o4, o5));
    u.w = h2_to_u(__floats2half2_rn(o6, o7));
    hout[node * 16 + lane] = u;
}

// ---------------- launch ------------------------------------------------------
static cudaStream_t s_gemm = nullptr;
static cudaEvent_t  s_fork = nullptr, s_join = nullptr;

extern "C" void kernel_launch(void* const* d_in, const int* in_sizes, int n_in,
                              void* d_out, int out_size) {
    const float* x  = (const float*)d_in[0];
    const void*  ei = d_in[1];
    const float* W1 = (const float*)d_in[2];
    const float* b1 = (const float*)d_in[3];
    const float* W2 = (const float*)d_in[4];
    const float* b2 = (const float*)d_in[5];
    float* out = (float*)d_out;

    void* p_hc = nullptr;
    cudaGetSymbolAddress(&p_hc, g_h16c);

    if (!s_gemm) {
        cudaStreamCreateWithFlags(&s_gemm, cudaStreamNonBlocking);
        cudaEventCreateWithFlags(&s_fork, cudaEventDisableTiming);
        cudaEventCreateWithFlags(&s_join, cudaEventDisableTiming);
    }

    const int T = 256;

    // fork: gemm1 runs concurrently with the CSR build chain
    cudaEventRecord(s_fork, 0);
    cudaStreamWaitEvent(s_gemm, s_fork, 0);
    gemm128<<<(NN + 127) / 128, 256, 0, s_gemm>>>(x, W1, b1, nullptr, 1, 0);
    cudaEventRecord(s_join, s_gemm);

    initdet<<<(NN + T - 1) / T, T>>>((const int*)ei);
    hist<<<(NE + T - 1) / T, T>>>(ei);
    scan1<<<(NN + 2047) / 2048, 256>>>();
    scanfix<<<(NN + T - 1) / T, T>>>();
    scatter<<<(TOT + T - 1) / T, T>>>(ei);

    cudaStreamWaitEvent(0, s_join, 0);

    for (int t = 0; t < 10; t++)
        propagate<<<(NN * 16 + T - 1) / T, T>>>(t);

    // final h is fp16 in g_h16c (t=9 wrote hout = g_h16c)
    gemm128<<<(NN + 127) / 128, 256>>>(p_hc, W2, b2, out, 0, 1);
}